// round 3
// baseline (speedup 1.0000x reference)
#include <cuda_runtime.h>
#include <cstdint>

// Problem constants
#define NB   2
#define NC   64
#define NH   32      // hidden = C/2
#define NX   64
#define NY   64
#define NZ   64
#define TABD 6
#define F32_EPS 1.1920928955078125e-07f

// Precomputed per-(b,c) tables, written by prep_kernel, read by mod_kernel.
__device__ float g_axs[NB * NC * NX];   // (1 - scale) * gauss_x
__device__ float g_gy [NB * NC * NY];   // gauss_y
__device__ float g_gz [NB * NC * NZ];   // gauss_z
__device__ float g_shift[NB * NC];

// ---------------------------------------------------------------------------
// Kernel 1: tiny MLP + param derivation + l2 + gaussian table precompute.
// One block, 256 threads. Total work ~ 25K exp/tanh evals — negligible.
// ---------------------------------------------------------------------------
__global__ void __launch_bounds__(256, 1)
prep_kernel(const float* __restrict__ tab,
            const float* __restrict__ w1, const float* __restrict__ b1,
            const float* __restrict__ w2, const float* __restrict__ b2,
            const float* __restrict__ wp, const float* __restrict__ bp,
            const float* __restrict__ ws, const float* __restrict__ bs,
            float* __restrict__ l2_out)
{
    __shared__ float s_emb [NB][NH];
    __shared__ float s_emb2[NB][NH];
    __shared__ float s_scale[NB][NC];
    __shared__ float s_shift[NB][NC];
    __shared__ float s_mu   [3][NB][NC];
    __shared__ float s_sigma[3][NB][NC];

    const int t = threadIdx.x;

    // Layer 1: emb = tanh(tab @ w1.T + b1)   -> [2,32], 64 threads
    if (t < NB * NH) {
        int b = t >> 5, j = t & 31;
        float acc = b1[j];
        #pragma unroll
        for (int k = 0; k < TABD; k++) acc += tab[b * TABD + k] * w1[j * TABD + k];
        s_emb[b][j] = tanhf(acc);
    }
    __syncthreads();

    // Layer 2: emb2 = tanh(emb @ w2.T + b2)  -> [2,32]
    if (t < NB * NH) {
        int b = t >> 5, j = t & 31;
        float acc = b2[j];
        #pragma unroll
        for (int k = 0; k < NH; k++) acc += s_emb[b][k] * w2[j * NH + k];
        s_emb2[b][j] = tanhf(acc);
    }
    __syncthreads();

    // Heads: p = emb2 @ wp.T + bp  [2,320];  s = sigmoid(emb2 @ ws.T + bs)  [2,192]
    // 640 + 384 = 1024 outputs, 4 per thread.
    for (int o = t; o < 1024; o += 256) {
        if (o < 640) {
            int b = o / 320, j = o % 320;
            float acc = bp[j];
            #pragma unroll
            for (int k = 0; k < NH; k++) acc += s_emb2[b][k] * wp[j * NH + k];
            int c   = j & 63;
            int grp = j >> 6;                 // 0:scale 1:shift 2..4:mu
            if      (grp == 0) s_scale[b][c] = acc;
            else if (grp == 1) s_shift[b][c] = acc;
            else               s_mu[grp - 2][b][c] = tanhf(acc);
        } else {
            int o2 = o - 640;
            int b = o2 / 192, j = o2 % 192;
            float acc = bs[j];
            #pragma unroll
            for (int k = 0; k < NH; k++) acc += s_emb2[b][k] * ws[j * NH + k];
            s_sigma[j >> 6][b][j & 63] = 1.0f / (1.0f + expf(-acc));
        }
    }
    __syncthreads();

    // l2 = ||scale||_F + ||shift||_F + ||sigma_a||_F + ||sigma_b||_F + ||sigma_c||_F
    // Single-warp reduction over 128 elements per tensor.
    if (t < 32) {
        float sums[5] = {0.f, 0.f, 0.f, 0.f, 0.f};
        for (int i = t; i < NB * NC; i += 32) {
            int b = i >> 6, c = i & 63;
            float v;
            v = s_scale[b][c];    sums[0] += v * v;
            v = s_shift[b][c];    sums[1] += v * v;
            v = s_sigma[0][b][c]; sums[2] += v * v;
            v = s_sigma[1][b][c]; sums[3] += v * v;
            v = s_sigma[2][b][c]; sums[4] += v * v;
        }
        #pragma unroll
        for (int s5 = 0; s5 < 5; s5++)
            #pragma unroll
            for (int off = 16; off > 0; off >>= 1)
                sums[s5] += __shfl_down_sync(0xffffffffu, sums[s5], off);
        if (t == 0 && l2_out != nullptr)
            *l2_out = sqrtf(sums[0]) + sqrtf(sums[1]) + sqrtf(sums[2])
                    + sqrtf(sums[3]) + sqrtf(sums[4]);
    }

    // Gaussian tables: 2*64 (b,c) x 3 axes x 64 coords = 24576 exps.
    // axis 0 gets (1 - scale) folded in.
    for (int o = t; o < NB * NC * 3 * 64; o += 256) {
        int i    = o & 63;
        int rest = o >> 6;          // 0..383
        int axis = rest % 3;
        int bc   = rest / 3;        // 0..127
        int b = bc >> 6, c = bc & 63;
        float mu = s_mu[axis][b][c];
        float sg = s_sigma[axis][b][c];
        // size = 64 on all axes:  mu' = mu*32 + 31.5 ; sigma' = sigma*3.5 + EPS
        float mup = mu * 32.0f + 31.5f;
        float sgp = sg * 3.5f + F32_EPS;
        float d   = ((float)i - mup) / sgp;
        float g   = expf(-0.5f * d * d);
        if      (axis == 0) g_axs[bc * 64 + i] = (1.0f - s_scale[b][c]) * g;
        else if (axis == 1) g_gy [bc * 64 + i] = g;
        else                g_gz [bc * 64 + i] = g;
    }
    if (t < NB * NC) g_shift[t] = s_shift[t >> 6][t & 63];
}

// ---------------------------------------------------------------------------
// Kernel 2: out[b,c,x,y,z] = x * ax[b,c,x] * gy[b,c,y] * gz[b,c,z] + shift[b,c]
// One block per (b,c,x) slice = 4096 contiguous floats. 256 threads, float4,
// streaming loads/stores (zero reuse -> bypass-friendly .cs hints).
// HBM-bound: 256 MiB traffic -> ~37 us at ~7.3 TB/s.
// ---------------------------------------------------------------------------
__global__ void __launch_bounds__(256, 8)
mod_kernel(const float* __restrict__ x, float* __restrict__ out)
{
    const int blk = blockIdx.x;        // 0 .. NB*NC*NX-1
    const int xi  = blk & 63;
    const int bc  = blk >> 6;          // 0 .. 127

    __shared__ __align__(16) float s_gy[NY];
    __shared__ __align__(16) float s_gz[NZ];

    const int t = threadIdx.x;
    if (t < 64)        s_gy[t]      = g_gy[bc * 64 + t];
    else if (t < 128)  s_gz[t - 64] = g_gz[bc * 64 + (t - 64)];

    const float ax = g_axs[bc * 64 + xi];  // (1-scale)*gx, scalar for this block
    const float sh = g_shift[bc];
    __syncthreads();

    const float4* __restrict__ xp = (const float4*)(x   + (size_t)blk * (NY * NZ));
    float4*       __restrict__ op = (float4*)      (out + (size_t)blk * (NY * NZ));

    #pragma unroll
    for (int it = 0; it < 4; it++) {
        int idx4 = t + it * 256;           // 0..1023 float4s in the yz-plane
        int y    = idx4 >> 4;              // 16 float4 per z-row
        int z4   = (idx4 & 15) << 2;
        float a  = ax * s_gy[y];
        float4 xv = __ldcs(&xp[idx4]);     // streaming load, no reuse
        float4 gz = *(const float4*)&s_gz[z4];
        float4 o;
        o.x = fmaf(xv.x, a * gz.x, sh);
        o.y = fmaf(xv.y, a * gz.y, sh);
        o.z = fmaf(xv.z, a * gz.z, sh);
        o.w = fmaf(xv.w, a * gz.w, sh);
        __stcs(&op[idx4], o);              // streaming store
    }
}

// ---------------------------------------------------------------------------
// Launch. Inputs (metadata order): x, tab, w1, b1, w2, b2, wp, bp, ws, bs.
// Output: out tensor [2,64,64,64,64] flattened, followed by scalar l2.
// ---------------------------------------------------------------------------
extern "C" void kernel_launch(void* const* d_in, const int* in_sizes, int n_in,
                              void* d_out, int out_size)
{
    const float* x   = (const float*)d_in[0];
    const float* tab = (const float*)d_in[1];
    const float* w1  = (const float*)d_in[2];
    const float* b1  = (const float*)d_in[3];
    const float* w2  = (const float*)d_in[4];
    const float* b2  = (const float*)d_in[5];
    const float* wp  = (const float*)d_in[6];
    const float* bp  = (const float*)d_in[7];
    const float* ws  = (const float*)d_in[8];
    const float* bs  = (const float*)d_in[9];

    float* out = (float*)d_out;
    const long long n_vol = (long long)NB * NC * NX * NY * NZ;  // 33,554,432
    float* l2_out = ((long long)out_size > n_vol) ? (out + n_vol) : nullptr;

    prep_kernel<<<1, 256>>>(tab, w1, b1, w2, b2, wp, bp, ws, bs, l2_out);
    mod_kernel<<<NB * NC * NX, 256>>>(x, out);
}

// round 4
// speedup vs baseline: 1.3660x; 1.3660x over previous
#include <cuda_runtime.h>
#include <cstdint>

#define NB   2
#define NC   64
#define NH   32
#define NX   64
#define NY   64
#define NZ   64
#define TABD 6
#define F32_EPS 1.1920928955078125e-07f

// Fused kernel: per-block MLP recompute + gaussian tables + streaming modulation.
// Grid: 1024 blocks = 128 (b,c) pairs x 8 x-groups. 256 threads.
// Block 0 additionally computes the scalar l2 (deterministic reduction).
__global__ void __launch_bounds__(256, 8)
fused_kernel(const float* __restrict__ x,
             const float* __restrict__ tab,
             const float* __restrict__ w1, const float* __restrict__ b1,
             const float* __restrict__ w2, const float* __restrict__ b2,
             const float* __restrict__ wp, const float* __restrict__ bp,
             const float* __restrict__ ws, const float* __restrict__ bs,
             float* __restrict__ out, float* __restrict__ l2_out)
{
    __shared__ float s_emb [NB][NH];
    __shared__ float s_emb2[NB][NH];
    __shared__ float s_param[8];            // 0:scale 1:shift 2-4:mu_abc 5-7:sigma_abc
    __shared__ __align__(16) float s_gy[NY];
    __shared__ __align__(16) float s_gz[NZ];
    __shared__ float s_ax[8];               // (1-scale)*gx for this block's 8 x-slices
    __shared__ float s_sq[640];             // block 0 only: squared params for l2

    const int t    = threadIdx.x;
    const int lane = t & 31;
    const int warp = t >> 5;                // 0..7
    const int bc   = blockIdx.x >> 3;       // 0..127
    const int xg   = blockIdx.x & 7;        // 0..7
    const int b    = bc >> 6;
    const int c    = bc & 63;

    // ---- MLP layer 1: emb = tanh(tab @ w1.T + b1)  [2,32] ----
    if (t < NB * NH) {
        int bb = t >> 5, j = t & 31;
        float acc = b1[j];
        #pragma unroll
        for (int k = 0; k < TABD; k++) acc += tab[bb * TABD + k] * w1[j * TABD + k];
        s_emb[bb][j] = tanhf(acc);
    }
    __syncthreads();

    // ---- MLP layer 2: emb2 = tanh(emb @ w2.T + b2)  [2,32] ----
    if (t < NB * NH) {
        int bb = t >> 5, j = t & 31;
        float acc = b2[j];
        #pragma unroll
        for (int k = 0; k < NH; k++) acc += s_emb[bb][k] * w2[j * NH + k];
        s_emb2[bb][j] = tanhf(acc);
    }
    __syncthreads();

    // ---- Heads for THIS block's (b,c): 8 warp-dot products ----
    // warp 0: scale    (wp row c)
    // warp 1: shift    (wp row 64+c)
    // warp 2-4: mu_abc (wp rows 128+c,192+c,256+c, tanh)
    // warp 5-7: sig_abc(ws rows c,64+c,128+c, sigmoid)
    {
        float e = s_emb2[b][lane];
        float wgt;
        float bias;
        if (warp < 5) {
            int row = warp * 64 + c;
            wgt = wp[row * NH + lane];
            bias = bp[row];
        } else {
            int row = (warp - 5) * 64 + c;
            wgt = ws[row * NH + lane];
            bias = bs[row];
        }
        float acc = e * wgt;
        #pragma unroll
        for (int off = 16; off > 0; off >>= 1)
            acc += __shfl_down_sync(0xffffffffu, acc, off);
        if (lane == 0) {
            acc += bias;
            if (warp >= 2 && warp <= 4)      acc = tanhf(acc);
            else if (warp >= 5)              acc = 1.0f / (1.0f + expf(-acc));
            s_param[warp] = acc;
        }
    }
    __syncthreads();

    // ---- Gaussian tables for this block ----
    if (t < 64) {                       // gy
        float mup = s_param[3] * 32.0f + 31.5f;
        float sgp = s_param[6] * 3.5f + F32_EPS;
        float d = ((float)t - mup) / sgp;
        s_gy[t] = __expf(-0.5f * d * d);
    } else if (t < 128) {               // gz
        int i = t - 64;
        float mup = s_param[4] * 32.0f + 31.5f;
        float sgp = s_param[7] * 3.5f + F32_EPS;
        float d = ((float)i - mup) / sgp;
        s_gz[i] = __expf(-0.5f * d * d);
    } else if (t < 136) {               // ax = (1-scale)*gx for 8 x-slices
        int xi = xg * 8 + (t - 128);
        float mup = s_param[2] * 32.0f + 31.5f;
        float sgp = s_param[5] * 3.5f + F32_EPS;
        float d = ((float)xi - mup) / sgp;
        s_ax[t - 128] = (1.0f - s_param[0]) * __expf(-0.5f * d * d);
    }

    // ---- Block 0 only: l2 over all 128 (b,c) x {scale,shift,sigma_a,b,c} ----
    if (blockIdx.x == 0) {
        for (int o = t; o < 640; o += 256) {
            int g = o >> 7;             // 0:scale 1:shift 2-4:sigma
            int r = o & 127;
            int bb = r >> 6, cc = r & 63;
            float acc, v;
            if (g < 2) {
                int row = g * 64 + cc;
                acc = bp[row];
                #pragma unroll
                for (int k = 0; k < NH; k++) acc += s_emb2[bb][k] * wp[row * NH + k];
                v = acc;
            } else {
                int row = (g - 2) * 64 + cc;
                acc = bs[row];
                #pragma unroll
                for (int k = 0; k < NH; k++) acc += s_emb2[bb][k] * ws[row * NH + k];
                v = 1.0f / (1.0f + expf(-acc));
            }
            s_sq[o] = v * v;
        }
        __syncthreads();
        if (t < 32) {
            float total = 0.0f;
            #pragma unroll
            for (int g = 0; g < 5; g++) {
                float s = s_sq[g * 128 + t] + s_sq[g * 128 + t + 32]
                        + s_sq[g * 128 + t + 64] + s_sq[g * 128 + t + 96];
                #pragma unroll
                for (int off = 16; off > 0; off >>= 1)
                    s += __shfl_down_sync(0xffffffffu, s, off);
                total += sqrtf(s);
            }
            if (t == 0 && l2_out != nullptr) *l2_out = total;
        }
    }
    __syncthreads();

    // ---- Streaming modulation: 8 x-planes of 4096 floats each ----
    const size_t base = (size_t)(bc * 64 + xg * 8) * 4096;
    const float4* __restrict__ xp = (const float4*)(x   + base);
    float4*       __restrict__ op = (float4*)      (out + base);
    const float sh = s_param[1];

    #pragma unroll
    for (int it = 0; it < 4; it++) {
        int idx4 = t + it * 256;            // 0..1023 float4 within a plane
        int y    = idx4 >> 4;
        int z4   = (idx4 & 15) << 2;
        float gyv = s_gy[y];
        float4 gz = *(const float4*)&s_gz[z4];
        #pragma unroll
        for (int p = 0; p < 8; p++) {
            float a = s_ax[p] * gyv;
            float4 xv = __ldcs(&xp[p * 1024 + idx4]);
            float4 o;
            o.x = fmaf(xv.x, a * gz.x, sh);
            o.y = fmaf(xv.y, a * gz.y, sh);
            o.z = fmaf(xv.z, a * gz.z, sh);
            o.w = fmaf(xv.w, a * gz.w, sh);
            __stcs(&op[p * 1024 + idx4], o);
        }
    }
}

extern "C" void kernel_launch(void* const* d_in, const int* in_sizes, int n_in,
                              void* d_out, int out_size)
{
    const float* x   = (const float*)d_in[0];
    const float* tab = (const float*)d_in[1];
    const float* w1  = (const float*)d_in[2];
    const float* b1  = (const float*)d_in[3];
    const float* w2  = (const float*)d_in[4];
    const float* b2  = (const float*)d_in[5];
    const float* wp  = (const float*)d_in[6];
    const float* bp  = (const float*)d_in[7];
    const float* ws  = (const float*)d_in[8];
    const float* bs  = (const float*)d_in[9];

    float* out = (float*)d_out;
    const long long n_vol = (long long)NB * NC * NX * NY * NZ;  // 33,554,432
    float* l2_out = ((long long)out_size > n_vol) ? (out + n_vol) : nullptr;

    fused_kernel<<<1024, 256>>>(x, tab, w1, b1, w2, b2, wp, bp, ws, bs, out, l2_out);
}